// round 12
// baseline (speedup 1.0000x reference)
#include <cuda_runtime.h>

// 2-layer LSTM (B=2048, T=1024, I=6, H=38) + projection (C=8), fp32.
// grid=128 persistent blocks, 16 batches/block, 640 threads, ONE barrier/step.
//   group A (0..319):   layer 0 @ step t
//   group B (320..639): layer 1 @ step t-1
// x/h0/h1 double-buffered by parity: reads p, writes nb, 1 __syncthreads/step.
// Thread = (px 0..7, q 0..39), owns a batch PAIR. Warp = 4 q x 8 px so both
// smem operands are 64B/warp:  W LDS.128 (4 consecutive q rows),
//                              h LDS.64  (8 px pairs).
// Per k: 1 LDS.128 + 1 LDS.64 + 2 ALU splats + 4 fma.rn.f32x2 = 8 MACs.
// 20 warps/SM (5/SMSP) for latency hiding.

namespace {
constexpr int Bsz = 2048, Tt = 1024, NI = 6, H = 38, HP = 40, Cc = 8;
constexpr int BT = 16;             // batches per block
constexpr int NPX = 8;             // px per group (batch pairs)
constexpr int GRP = NPX * HP;      // 320 threads per group
constexpr int NTHR = 2 * GRP;      // 640
constexpr int WAN = (NI + HP) * HP * 4;   // 7360 floats
constexpr int WBN = (HP + HP) * HP * 4;   // 12800 floats
// s0 rows: x dbl-buf [0..2*NI), h0 dbl-buf [2*NI..2*NI+2*HP)
// s1 rows: h1 dbl-buf [0..2*HP)
constexpr int S0ROWS = 2 * NI + 2 * HP;   // 92
constexpr int S1ROWS = 2 * HP;            // 80
constexpr int S0N = S0ROWS * BT;          // 1472
constexpr int S1N = S1ROWS * BT;          // 1280
constexpr int SMEM_FLOATS = WAN + WBN + S0N + S1N;  // 22912 -> 91648 B
}

typedef unsigned long long ull;

__device__ __forceinline__ ull pk2(float a, float b) {
    ull r; asm("mov.b64 %0, {%1, %2};" : "=l"(r) : "f"(a), "f"(b)); return r;
}
__device__ __forceinline__ ull splat(float v) {
    ull r; asm("mov.b64 %0, {%1, %1};" : "=l"(r) : "f"(v)); return r;
}
__device__ __forceinline__ void fma2(ull &d, ull a, ull b) {
    asm("fma.rn.f32x2 %0, %1, %2, %0;" : "+l"(d) : "l"(a), "l"(b));
}
__device__ __forceinline__ void unpk2(ull v, float &a, float &b) {
    asm("mov.b64 {%0, %1}, %2;" : "=f"(a), "=f"(b) : "l"(v));
}
__device__ __forceinline__ float sigm(float x) {
    return __fdividef(1.0f, 1.0f + __expf(-x));
}
__device__ __forceinline__ float tanh_(float x) {
    return __fdividef(2.0f, 1.0f + __expf(-2.0f * x)) - 1.0f;
}

// 40-k gate accumulation over one state buffer half (batch pair)
__device__ __forceinline__ void acc40(const float* __restrict__ hbase,
                                      const float* __restrict__ wbase,
                                      ull &aif0, ull &ago0, ull &aif1, ull &ago1) {
    #pragma unroll
    for (int k = 0; k < HP; ++k) {
        float2 hp = *(const float2*)(hbase + k * BT);                 // {h_b0,h_b1}
        ulonglong2 w = *(const ulonglong2*)(wbase + k * (4 * HP));    // {wi,wf},{wg,wo}
        ull h0s = splat(hp.x), h1s = splat(hp.y);
        fma2(aif0, h0s, w.x); fma2(ago0, h0s, w.y);
        fma2(aif1, h1s, w.x); fma2(ago1, h1s, w.y);
    }
}

__global__ void __launch_bounds__(NTHR, 1) lstm_kernel(
    const float* __restrict__ x,    const float* __restrict__ Wih0,
    const float* __restrict__ Whh0, const float* __restrict__ b0,
    const float* __restrict__ Wih1, const float* __restrict__ Whh1,
    const float* __restrict__ b1,   const float* __restrict__ Wc,
    const float* __restrict__ bc,   float* __restrict__ out)
{
    extern __shared__ float sm[];
    float* WA = sm;             // [k][q][4]={wi,wf,wg,wo}, k: 0..5 x, 6..45 h0
    float* WB = WA + WAN;       // [k][q][4],               k: 0..39 h0, 40..79 h1
    float* s0 = WB + WBN;       // x dbl-buf rows + h0 dbl-buf rows
    float* s1 = s0 + S0N;       // h1 dbl-buf rows

    const int tid = threadIdx.x;
    const int grp = tid >= GRP;          // 0 = layer0 (A), 1 = layer1 (B)
    const int lt  = tid - grp * GRP;
    const int px  = lt & 7;              // 0..7 batch pair
    const int q   = lt >> 3;             // 0..39 (warp = 4 q x 8 px)
    const int bb0 = blockIdx.x * BT + 2 * px;

    // ---- stage weights (zero-padded units / k rows) ----
    for (int idx = tid; idx < WAN; idx += NTHR) {
        int g = idx & 3, qq = (idx >> 2) % HP, k = idx / (4 * HP);
        float v = 0.0f;
        if (qq < H) {
            int row = g * H + qq;
            if (k < NI)          v = Wih0[row * NI + k];
            else { int kk = k - NI; if (kk < H) v = Whh0[row * H + kk]; }
        }
        WA[idx] = v;
    }
    for (int idx = tid; idx < WBN; idx += NTHR) {
        int g = idx & 3, qq = (idx >> 2) % HP, k = idx / (4 * HP);
        float v = 0.0f;
        if (qq < H) {
            int row = g * H + qq;
            if (k < HP) { if (k < H) v = Wih1[row * H + k]; }
            else        { int kk = k - HP; if (kk < H) v = Whh1[row * H + kk]; }
        }
        WB[idx] = v;
    }
    for (int idx = tid; idx < S0N; idx += NTHR) s0[idx] = 0.0f;
    for (int idx = tid; idx < S1N; idx += NTHR) s1[idx] = 0.0f;

    // ---- per-thread packed biases for this thread's layer ----
    ull bif, bgo;
    if (q < H) {
        const float* b = grp ? b1 : b0;
        bif = pk2(b[q], b[H + q]);
        bgo = pk2(b[2 * H + q], b[3 * H + q]);
    } else {
        bif = bgo = pk2(0.0f, 0.0f);
    }

    // ---- x(0) into x buffer 0 ----
    if (grp == 0 && q < NI) {
        float x0 = x[(size_t)(bb0 + 0) * Tt * NI + q];
        float x1 = x[(size_t)(bb0 + 1) * Tt * NI + q];
        *(float2*)(s0 + q * BT + 2 * px) = make_float2(x0, x1);
    }
    __syncthreads();

    float c0s = 0.0f, c1s = 0.0f;        // this thread's layer cell state, 2 batches
    const int hoff = 2 * px;

    // iteration it: A computes layer0 step it (it < Tt);
    //               B computes layer1 step it-1 (it >= 1).
    for (int it = 0; it <= Tt; ++it) {
        const int p  = it & 1;
        const int nb = p ^ 1;

        if (grp == 0) {
            if (it < Tt) {
                // x_{t+1} prefetch (in flight during compute)
                float xn0 = 0.f, xn1 = 0.f;
                if (q < NI && it + 1 < Tt) {
                    size_t o = (size_t)(it + 1) * NI + q;
                    xn0 = x[(size_t)(bb0 + 0) * Tt * NI + o];
                    xn1 = x[(size_t)(bb0 + 1) * Tt * NI + o];
                }
                ull aif0 = bif, ago0 = bgo, aif1 = bif, ago1 = bgo;
                const float* wa = WA + 4 * q;
                const float* hx = s0 + p * NI * BT + hoff;      // x buf p
                #pragma unroll
                for (int k = 0; k < NI; ++k) {
                    float2 hp = *(const float2*)(hx + k * BT);
                    ulonglong2 w = *(const ulonglong2*)(wa + k * (4 * HP));
                    ull h0s = splat(hp.x), h1s = splat(hp.y);
                    fma2(aif0, h0s, w.x); fma2(ago0, h0s, w.y);
                    fma2(aif1, h1s, w.x); fma2(ago1, h1s, w.y);
                }
                acc40(s0 + (2 * NI + p * HP) * BT + hoff,       // h0 buf p
                      WA + NI * (4 * HP) + 4 * q, aif0, ago0, aif1, ago1);
                float gi0, gf0, gg0, go0, gi1, gf1, gg1, go1;
                unpk2(aif0, gi0, gf0); unpk2(ago0, gg0, go0);
                unpk2(aif1, gi1, gf1); unpk2(ago1, gg1, go1);
                float i0 = sigm(gi0), f0 = sigm(gf0), g0 = tanh_(gg0), o0 = sigm(go0);
                c0s = f0 * c0s + i0 * g0;
                float h00 = o0 * tanh_(c0s);
                float i1 = sigm(gi1), f1 = sigm(gf1), g1 = tanh_(gg1), o1 = sigm(go1);
                c1s = f1 * c1s + i1 * g1;
                float h01 = o1 * tanh_(c1s);
                // writes -> nb buffers only
                *(float2*)(s0 + (2 * NI + nb * HP + q) * BT + hoff) = make_float2(h00, h01);
                if (q < NI && it + 1 < Tt)
                    *(float2*)(s0 + (nb * NI + q) * BT + hoff) = make_float2(xn0, xn1);
            }
        } else {
            if (it >= 1) {
                ull aif0 = bif, ago0 = bgo, aif1 = bif, ago1 = bgo;
                // h0(it-1) in s0 h0 buf p (same rows A reads)
                acc40(s0 + (2 * NI + p * HP) * BT + hoff, WB + 4 * q,
                      aif0, ago0, aif1, ago1);
                // h1(it-2) in s1 buf p
                acc40(s1 + p * HP * BT + hoff, WB + HP * (4 * HP) + 4 * q,
                      aif0, ago0, aif1, ago1);
                float gi0, gf0, gg0, go0, gi1, gf1, gg1, go1;
                unpk2(aif0, gi0, gf0); unpk2(ago0, gg0, go0);
                unpk2(aif1, gi1, gf1); unpk2(ago1, gg1, go1);
                float i0 = sigm(gi0), f0 = sigm(gf0), g0 = tanh_(gg0), o0 = sigm(go0);
                c0s = f0 * c0s + i0 * g0;
                float h10 = o0 * tanh_(c0s);
                float i1 = sigm(gi1), f1 = sigm(gf1), g1 = tanh_(gg1), o1 = sigm(go1);
                c1s = f1 * c1s + i1 * g1;
                float h11 = o1 * tanh_(c1s);
                *(float2*)(s1 + (nb * HP + q) * BT + hoff) = make_float2(h10, h11);
            }
        }

        __syncthreads();   // single barrier: nb writes visible, p reads done
    }

    // ---- final projection from h1(Tt-1) in buf (Tt+1)&1 ----
    if (grp == 0 && q < Cc) {
        const int bufL = (Tt + 1) & 1;
        const float* hl = s1 + bufL * HP * BT + hoff;
        float a0 = bc[q], a1 = a0;
        #pragma unroll
        for (int k = 0; k < H; ++k) {
            float w = Wc[q * H + k];
            float2 hv = *(const float2*)(hl + k * BT);
            a0 += w * hv.x;
            a1 += w * hv.y;
        }
        out[(size_t)(bb0 + 0) * Cc + q] = a0;
        out[(size_t)(bb0 + 1) * Cc + q] = a1;
    }
}

extern "C" void kernel_launch(void* const* d_in, const int* in_sizes, int n_in,
                              void* d_out, int out_size) {
    const float* x    = (const float*)d_in[0];
    const float* Wih0 = (const float*)d_in[1];
    const float* Whh0 = (const float*)d_in[2];
    const float* b0   = (const float*)d_in[3];
    const float* Wih1 = (const float*)d_in[4];
    const float* Whh1 = (const float*)d_in[5];
    const float* b1   = (const float*)d_in[6];
    const float* Wc   = (const float*)d_in[7];
    const float* bc   = (const float*)d_in[8];

    const int smem_bytes = SMEM_FLOATS * (int)sizeof(float);
    cudaFuncSetAttribute(lstm_kernel, cudaFuncAttributeMaxDynamicSharedMemorySize, smem_bytes);
    lstm_kernel<<<Bsz / BT, NTHR, smem_bytes>>>(
        x, Wih0, Whh0, b0, Wih1, Whh1, b1, Wc, bc, (float*)d_out);
}

// round 13
// speedup vs baseline: 1.0451x; 1.0451x over previous
#include <cuda_runtime.h>

// 2-layer LSTM (B=2048, T=1024, I=6, H=38) + projection (C=8), fp32.
// grid=256 persistent blocks, 8 batches/block, 160 threads, TWO blocks/SM:
// independent barrier domains per block overlap each other's MUFU-tail and
// barrier bubbles on the same SM (108 SMs hold 2 blocks, 40 hold 1).
//   group A (0..79):   layer 0 @ step t
//   group B (80..159): layer 1 @ step t-1
// x/h0/h1 double-buffered by parity: reads p, writes nb, 1 barrier/step.
// Thread = (px 0..1, q 0..39), owns 4 batches. Per k:
//   1x LDS.128 W[k][q] + 1x LDS.128 h + 4 ALU splats + 8 fma.rn.f32x2 = 16 MACs.

namespace {
constexpr int Bsz = 2048, Tt = 1024, NI = 6, H = 38, HP = 40, Cc = 8;
constexpr int BT = 8;              // batches per block
constexpr int NPX = 2;             // px threads per group (4 batches each)
constexpr int GRP = NPX * HP;      // 80 threads per group
constexpr int NTHR = 2 * GRP;      // 160
constexpr int WAN = (NI + HP) * HP * 4;   // 7360 floats
constexpr int WBN = (HP + HP) * HP * 4;   // 12800 floats
// s0 rows (BT floats each): x dbl-buf [0..2*NI), h0 dbl-buf [2*NI..2*NI+2*HP)
// s1 rows: h1 dbl-buf [0..2*HP)
constexpr int S0ROWS = 2 * NI + 2 * HP;   // 92
constexpr int S1ROWS = 2 * HP;            // 80
constexpr int S0N = S0ROWS * BT;          // 736
constexpr int S1N = S1ROWS * BT;          // 640
constexpr int SMEM_FLOATS = WAN + WBN + S0N + S1N;  // 21536 -> 86144 B/block
}

typedef unsigned long long ull;

__device__ __forceinline__ ull pk2(float a, float b) {
    ull r; asm("mov.b64 %0, {%1, %2};" : "=l"(r) : "f"(a), "f"(b)); return r;
}
__device__ __forceinline__ ull splat(float v) {
    ull r; asm("mov.b64 %0, {%1, %1};" : "=l"(r) : "f"(v)); return r;
}
__device__ __forceinline__ void fma2(ull &d, ull a, ull b) {
    asm("fma.rn.f32x2 %0, %1, %2, %0;" : "+l"(d) : "l"(a), "l"(b));
}
__device__ __forceinline__ void unpk2(ull v, float &a, float &b) {
    asm("mov.b64 {%0, %1}, %2;" : "=f"(a), "=f"(b) : "l"(v));
}
__device__ __forceinline__ float sigm(float x) {
    return __fdividef(1.0f, 1.0f + __expf(-x));
}
__device__ __forceinline__ float tanh_(float x) {
    return __fdividef(2.0f, 1.0f + __expf(-2.0f * x)) - 1.0f;
}

// 40-k gate accumulation over one state buffer half (4 batches)
__device__ __forceinline__ void acc40(const float* __restrict__ hbase,
                                      const float* __restrict__ wbase,
                                      ull aif[4], ull ago[4]) {
    #pragma unroll
    for (int k = 0; k < HP; ++k) {
        float4 hv = *(const float4*)(hbase + k * BT);
        ulonglong2 w = *(const ulonglong2*)(wbase + k * (4 * HP));
        ull h0s = splat(hv.x), h1s = splat(hv.y), h2s = splat(hv.z), h3s = splat(hv.w);
        fma2(aif[0], h0s, w.x); fma2(ago[0], h0s, w.y);
        fma2(aif[1], h1s, w.x); fma2(ago[1], h1s, w.y);
        fma2(aif[2], h2s, w.x); fma2(ago[2], h2s, w.y);
        fma2(aif[3], h3s, w.x); fma2(ago[3], h3s, w.y);
    }
}

__global__ void __launch_bounds__(NTHR, 2) lstm_kernel(
    const float* __restrict__ x,    const float* __restrict__ Wih0,
    const float* __restrict__ Whh0, const float* __restrict__ b0,
    const float* __restrict__ Wih1, const float* __restrict__ Whh1,
    const float* __restrict__ b1,   const float* __restrict__ Wc,
    const float* __restrict__ bc,   float* __restrict__ out)
{
    extern __shared__ float sm[];
    float* WA = sm;             // [k][q][4]={wi,wf,wg,wo}, k: 0..5 x, 6..45 h0
    float* WB = WA + WAN;       // [k][q][4],               k: 0..39 h0, 40..79 h1
    float* s0 = WB + WBN;       // x dbl-buf rows + h0 dbl-buf rows
    float* s1 = s0 + S0N;       // h1 dbl-buf rows

    const int tid = threadIdx.x;
    const int grp = tid >= GRP;          // 0 = layer0 (A), 1 = layer1 (B)
    const int lt  = tid - grp * GRP;
    const int px  = lt & 1;              // 0..1, 4 batches each
    const int q   = lt >> 1;             // 0..39 (warp = 16 q x 2 px)
    const int bb0 = blockIdx.x * BT + 4 * px;

    // ---- stage weights (zero-padded units / k rows) ----
    for (int idx = tid; idx < WAN; idx += NTHR) {
        int g = idx & 3, qq = (idx >> 2) % HP, k = idx / (4 * HP);
        float v = 0.0f;
        if (qq < H) {
            int row = g * H + qq;
            if (k < NI)          v = Wih0[row * NI + k];
            else { int kk = k - NI; if (kk < H) v = Whh0[row * H + kk]; }
        }
        WA[idx] = v;
    }
    for (int idx = tid; idx < WBN; idx += NTHR) {
        int g = idx & 3, qq = (idx >> 2) % HP, k = idx / (4 * HP);
        float v = 0.0f;
        if (qq < H) {
            int row = g * H + qq;
            if (k < HP) { if (k < H) v = Wih1[row * H + k]; }
            else        { int kk = k - HP; if (kk < H) v = Whh1[row * H + kk]; }
        }
        WB[idx] = v;
    }
    for (int idx = tid; idx < S0N; idx += NTHR) s0[idx] = 0.0f;
    for (int idx = tid; idx < S1N; idx += NTHR) s1[idx] = 0.0f;

    // ---- per-thread packed biases for this thread's layer ----
    ull bif, bgo;
    if (q < H) {
        const float* b = grp ? b1 : b0;
        bif = pk2(b[q], b[H + q]);
        bgo = pk2(b[2 * H + q], b[3 * H + q]);
    } else {
        bif = bgo = pk2(0.0f, 0.0f);
    }

    // ---- x(0) into x buffer 0 ----
    if (grp == 0 && q < NI) {
        float4 xv;
        xv.x = x[(size_t)(bb0 + 0) * Tt * NI + q];
        xv.y = x[(size_t)(bb0 + 1) * Tt * NI + q];
        xv.z = x[(size_t)(bb0 + 2) * Tt * NI + q];
        xv.w = x[(size_t)(bb0 + 3) * Tt * NI + q];
        *(float4*)(s0 + q * BT + 4 * px) = xv;
    }
    __syncthreads();

    float cst[4] = {0.f, 0.f, 0.f, 0.f};   // A: layer-0 c; B: layer-1 c
    const int hoff = 4 * px;

    // iteration it: A computes layer0 step it (it < Tt);
    //               B computes layer1 step it-1 (it >= 1).
    for (int it = 0; it <= Tt; ++it) {
        const int p  = it & 1;
        const int nb = p ^ 1;

        if (grp == 0) {
            if (it < Tt) {
                // x_{t+1} prefetch (in flight during compute)
                float xn0 = 0.f, xn1 = 0.f, xn2 = 0.f, xn3 = 0.f;
                if (q < NI && it + 1 < Tt) {
                    size_t o = (size_t)(it + 1) * NI + q;
                    xn0 = x[(size_t)(bb0 + 0) * Tt * NI + o];
                    xn1 = x[(size_t)(bb0 + 1) * Tt * NI + o];
                    xn2 = x[(size_t)(bb0 + 2) * Tt * NI + o];
                    xn3 = x[(size_t)(bb0 + 3) * Tt * NI + o];
                }
                ull aif[4], ago[4];
                #pragma unroll
                for (int j = 0; j < 4; ++j) { aif[j] = bif; ago[j] = bgo; }
                const float* wa = WA + 4 * q;
                const float* hx = s0 + p * NI * BT + hoff;      // x buf p
                #pragma unroll
                for (int k = 0; k < NI; ++k) {
                    float4 hv = *(const float4*)(hx + k * BT);
                    ulonglong2 w = *(const ulonglong2*)(wa + k * (4 * HP));
                    ull h0s = splat(hv.x), h1s = splat(hv.y), h2s = splat(hv.z), h3s = splat(hv.w);
                    fma2(aif[0], h0s, w.x); fma2(ago[0], h0s, w.y);
                    fma2(aif[1], h1s, w.x); fma2(ago[1], h1s, w.y);
                    fma2(aif[2], h2s, w.x); fma2(ago[2], h2s, w.y);
                    fma2(aif[3], h3s, w.x); fma2(ago[3], h3s, w.y);
                }
                acc40(s0 + (2 * NI + p * HP) * BT + hoff,       // h0 buf p
                      WA + NI * (4 * HP) + 4 * q, aif, ago);
                float hr[4];
                #pragma unroll
                for (int j = 0; j < 4; ++j) {
                    float gi, gf, gg, go;
                    unpk2(aif[j], gi, gf); unpk2(ago[j], gg, go);
                    float i = sigm(gi), f = sigm(gf), g = tanh_(gg), o = sigm(go);
                    cst[j] = f * cst[j] + i * g;
                    hr[j] = o * tanh_(cst[j]);
                }
                // writes -> nb buffers only
                *(float4*)(s0 + (2 * NI + nb * HP + q) * BT + hoff) =
                    make_float4(hr[0], hr[1], hr[2], hr[3]);
                if (q < NI && it + 1 < Tt)
                    *(float4*)(s0 + (nb * NI + q) * BT + hoff) =
                        make_float4(xn0, xn1, xn2, xn3);
            }
        } else {
            if (it >= 1) {
                ull aif[4], ago[4];
                #pragma unroll
                for (int j = 0; j < 4; ++j) { aif[j] = bif; ago[j] = bgo; }
                // h0(it-1) in s0 h0 buf p (same rows A reads)
                acc40(s0 + (2 * NI + p * HP) * BT + hoff, WB + 4 * q, aif, ago);
                // h1(it-2) in s1 buf p
                acc40(s1 + p * HP * BT + hoff, WB + HP * (4 * HP) + 4 * q, aif, ago);
                float hr[4];
                #pragma unroll
                for (int j = 0; j < 4; ++j) {
                    float gi, gf, gg, go;
                    unpk2(aif[j], gi, gf); unpk2(ago[j], gg, go);
                    float i = sigm(gi), f = sigm(gf), g = tanh_(gg), o = sigm(go);
                    cst[j] = f * cst[j] + i * g;
                    hr[j] = o * tanh_(cst[j]);
                }
                *(float4*)(s1 + (nb * HP + q) * BT + hoff) =
                    make_float4(hr[0], hr[1], hr[2], hr[3]);
            }
        }

        __syncthreads();   // single per-block barrier (160 threads)
    }

    // ---- final projection from h1(Tt-1) in buf (Tt+1)&1 ----
    if (grp == 0 && q < Cc) {
        const int bufL = (Tt + 1) & 1;
        const float* hl = s1 + bufL * HP * BT + hoff;
        float a0 = bc[q], a1 = a0, a2 = a0, a3 = a0;
        #pragma unroll
        for (int k = 0; k < H; ++k) {
            float w = Wc[q * H + k];
            float4 hv = *(const float4*)(hl + k * BT);
            a0 += w * hv.x; a1 += w * hv.y; a2 += w * hv.z; a3 += w * hv.w;
        }
        out[(size_t)(bb0 + 0) * Cc + q] = a0;
        out[(size_t)(bb0 + 1) * Cc + q] = a1;
        out[(size_t)(bb0 + 2) * Cc + q] = a2;
        out[(size_t)(bb0 + 3) * Cc + q] = a3;
    }
}

extern "C" void kernel_launch(void* const* d_in, const int* in_sizes, int n_in,
                              void* d_out, int out_size) {
    const float* x    = (const float*)d_in[0];
    const float* Wih0 = (const float*)d_in[1];
    const float* Whh0 = (const float*)d_in[2];
    const float* b0   = (const float*)d_in[3];
    const float* Wih1 = (const float*)d_in[4];
    const float* Whh1 = (const float*)d_in[5];
    const float* b1   = (const float*)d_in[6];
    const float* Wc   = (const float*)d_in[7];
    const float* bc   = (const float*)d_in[8];

    const int smem_bytes = SMEM_FLOATS * (int)sizeof(float);
    cudaFuncSetAttribute(lstm_kernel, cudaFuncAttributeMaxDynamicSharedMemorySize, smem_bytes);
    lstm_kernel<<<Bsz / BT, NTHR, smem_bytes>>>(
        x, Wih0, Whh0, b0, Wih1, Whh1, b1, Wc, bc, (float*)d_out);
}

// round 14
// speedup vs baseline: 1.0547x; 1.0092x over previous
#include <cuda_runtime.h>

// 2-layer LSTM (B=2048, T=1024, I=6, H=38) + projection (C=8), fp32.
// grid=256 persistent blocks, 8 batches/block, 192 threads, TWO blocks/SM.
// WARP-ALIGNED layer groups (fixes R13's straddling divergent warp):
//   group A = warps 0-2 (threads  0..95, active lt<80): layer 0 @ step t
//   group B = warps 3-5 (threads 96..191, active lt<80): layer 1 @ step t-1
// x/h0/h1 double-buffered by parity: reads p, writes nb, 1 barrier/step.
// Active thread = (px 0..1, q 0..39), owns 4 batches. Per k:
//   1x LDS.128 W[k][q] + 1x LDS.128 h + 4 ALU splats + 8 fma.rn.f32x2 = 16 MACs.

namespace {
constexpr int Bsz = 2048, Tt = 1024, NI = 6, H = 38, HP = 40, Cc = 8;
constexpr int BT = 8;              // batches per block
constexpr int GRPT = 96;           // threads per group (3 warps, 80 active)
constexpr int GACT = 80;           // active threads per group
constexpr int NTHR = 2 * GRPT;     // 192
constexpr int WAN = (NI + HP) * HP * 4;   // 7360 floats
constexpr int WBN = (HP + HP) * HP * 4;   // 12800 floats
// s0 rows (BT floats each): x dbl-buf [0..2*NI), h0 dbl-buf [2*NI..2*NI+2*HP)
// s1 rows: h1 dbl-buf [0..2*HP)
constexpr int S0ROWS = 2 * NI + 2 * HP;   // 92
constexpr int S1ROWS = 2 * HP;            // 80
constexpr int S0N = S0ROWS * BT;          // 736
constexpr int S1N = S1ROWS * BT;          // 640
constexpr int SMEM_FLOATS = WAN + WBN + S0N + S1N;  // 21536 -> 86144 B/block
}

typedef unsigned long long ull;

__device__ __forceinline__ ull pk2(float a, float b) {
    ull r; asm("mov.b64 %0, {%1, %2};" : "=l"(r) : "f"(a), "f"(b)); return r;
}
__device__ __forceinline__ ull splat(float v) {
    ull r; asm("mov.b64 %0, {%1, %1};" : "=l"(r) : "f"(v)); return r;
}
__device__ __forceinline__ void fma2(ull &d, ull a, ull b) {
    asm("fma.rn.f32x2 %0, %1, %2, %0;" : "+l"(d) : "l"(a), "l"(b));
}
__device__ __forceinline__ void unpk2(ull v, float &a, float &b) {
    asm("mov.b64 {%0, %1}, %2;" : "=f"(a), "=f"(b) : "l"(v));
}
__device__ __forceinline__ float sigm(float x) {
    return __fdividef(1.0f, 1.0f + __expf(-x));
}
__device__ __forceinline__ float tanh_(float x) {
    return __fdividef(2.0f, 1.0f + __expf(-2.0f * x)) - 1.0f;
}

// 40-k gate accumulation over one state buffer half (4 batches)
__device__ __forceinline__ void acc40(const float* __restrict__ hbase,
                                      const float* __restrict__ wbase,
                                      ull aif[4], ull ago[4]) {
    #pragma unroll
    for (int k = 0; k < HP; ++k) {
        float4 hv = *(const float4*)(hbase + k * BT);
        ulonglong2 w = *(const ulonglong2*)(wbase + k * (4 * HP));
        ull h0s = splat(hv.x), h1s = splat(hv.y), h2s = splat(hv.z), h3s = splat(hv.w);
        fma2(aif[0], h0s, w.x); fma2(ago[0], h0s, w.y);
        fma2(aif[1], h1s, w.x); fma2(ago[1], h1s, w.y);
        fma2(aif[2], h2s, w.x); fma2(ago[2], h2s, w.y);
        fma2(aif[3], h3s, w.x); fma2(ago[3], h3s, w.y);
    }
}

__global__ void __launch_bounds__(NTHR, 2) lstm_kernel(
    const float* __restrict__ x,    const float* __restrict__ Wih0,
    const float* __restrict__ Whh0, const float* __restrict__ b0,
    const float* __restrict__ Wih1, const float* __restrict__ Whh1,
    const float* __restrict__ b1,   const float* __restrict__ Wc,
    const float* __restrict__ bc,   float* __restrict__ out)
{
    extern __shared__ float sm[];
    float* WA = sm;             // [k][q][4]={wi,wf,wg,wo}, k: 0..5 x, 6..45 h0
    float* WB = WA + WAN;       // [k][q][4],               k: 0..39 h0, 40..79 h1
    float* s0 = WB + WBN;       // x dbl-buf rows + h0 dbl-buf rows
    float* s1 = s0 + S0N;       // h1 dbl-buf rows

    const int tid = threadIdx.x;
    const int grp = tid / GRPT;          // 0 = layer0 (A), 1 = layer1 (B)
    const int lt  = tid - grp * GRPT;
    const bool act = lt < GACT;          // lanes 80..95 of each group idle
    const int px  = lt & 1;              // 0..1, 4 batches each
    const int q   = lt >> 1;             // 0..47 (valid < 40 when act)
    const int bb0 = blockIdx.x * BT + 4 * px;

    // ---- stage weights (zero-padded units / k rows) ----
    for (int idx = tid; idx < WAN; idx += NTHR) {
        int g = idx & 3, qq = (idx >> 2) % HP, k = idx / (4 * HP);
        float v = 0.0f;
        if (qq < H) {
            int row = g * H + qq;
            if (k < NI)          v = Wih0[row * NI + k];
            else { int kk = k - NI; if (kk < H) v = Whh0[row * H + kk]; }
        }
        WA[idx] = v;
    }
    for (int idx = tid; idx < WBN; idx += NTHR) {
        int g = idx & 3, qq = (idx >> 2) % HP, k = idx / (4 * HP);
        float v = 0.0f;
        if (qq < H) {
            int row = g * H + qq;
            if (k < HP) { if (k < H) v = Wih1[row * H + k]; }
            else        { int kk = k - HP; if (kk < H) v = Whh1[row * H + kk]; }
        }
        WB[idx] = v;
    }
    for (int idx = tid; idx < S0N; idx += NTHR) s0[idx] = 0.0f;
    for (int idx = tid; idx < S1N; idx += NTHR) s1[idx] = 0.0f;

    // ---- per-thread packed biases for this thread's layer ----
    ull bif, bgo;
    if (act && q < H) {
        const float* b = grp ? b1 : b0;
        bif = pk2(b[q], b[H + q]);
        bgo = pk2(b[2 * H + q], b[3 * H + q]);
    } else {
        bif = bgo = pk2(0.0f, 0.0f);
    }

    // ---- x(0) into x buffer 0 ----
    if (grp == 0 && act && q < NI) {
        float4 xv;
        xv.x = x[(size_t)(bb0 + 0) * Tt * NI + q];
        xv.y = x[(size_t)(bb0 + 1) * Tt * NI + q];
        xv.z = x[(size_t)(bb0 + 2) * Tt * NI + q];
        xv.w = x[(size_t)(bb0 + 3) * Tt * NI + q];
        *(float4*)(s0 + q * BT + 4 * px) = xv;
    }
    __syncthreads();

    float cst[4] = {0.f, 0.f, 0.f, 0.f};   // A: layer-0 c; B: layer-1 c
    const int hoff = 4 * px;

    // iteration it: A computes layer0 step it (it < Tt);
    //               B computes layer1 step it-1 (it >= 1).
    for (int it = 0; it <= Tt; ++it) {
        const int p  = it & 1;
        const int nb = p ^ 1;

        if (grp == 0) {
            if (act && it < Tt) {
                // x_{t+1} prefetch (in flight during compute)
                float xn0 = 0.f, xn1 = 0.f, xn2 = 0.f, xn3 = 0.f;
                if (q < NI && it + 1 < Tt) {
                    size_t o = (size_t)(it + 1) * NI + q;
                    xn0 = x[(size_t)(bb0 + 0) * Tt * NI + o];
                    xn1 = x[(size_t)(bb0 + 1) * Tt * NI + o];
                    xn2 = x[(size_t)(bb0 + 2) * Tt * NI + o];
                    xn3 = x[(size_t)(bb0 + 3) * Tt * NI + o];
                }
                ull aif[4], ago[4];
                #pragma unroll
                for (int j = 0; j < 4; ++j) { aif[j] = bif; ago[j] = bgo; }
                const float* wa = WA + 4 * q;
                const float* hx = s0 + p * NI * BT + hoff;      // x buf p
                #pragma unroll
                for (int k = 0; k < NI; ++k) {
                    float4 hv = *(const float4*)(hx + k * BT);
                    ulonglong2 w = *(const ulonglong2*)(wa + k * (4 * HP));
                    ull h0s = splat(hv.x), h1s = splat(hv.y), h2s = splat(hv.z), h3s = splat(hv.w);
                    fma2(aif[0], h0s, w.x); fma2(ago[0], h0s, w.y);
                    fma2(aif[1], h1s, w.x); fma2(ago[1], h1s, w.y);
                    fma2(aif[2], h2s, w.x); fma2(ago[2], h2s, w.y);
                    fma2(aif[3], h3s, w.x); fma2(ago[3], h3s, w.y);
                }
                acc40(s0 + (2 * NI + p * HP) * BT + hoff,       // h0 buf p
                      WA + NI * (4 * HP) + 4 * q, aif, ago);
                float hr[4];
                #pragma unroll
                for (int j = 0; j < 4; ++j) {
                    float gi, gf, gg, go;
                    unpk2(aif[j], gi, gf); unpk2(ago[j], gg, go);
                    float i = sigm(gi), f = sigm(gf), g = tanh_(gg), o = sigm(go);
                    cst[j] = f * cst[j] + i * g;
                    hr[j] = o * tanh_(cst[j]);
                }
                // writes -> nb buffers only
                *(float4*)(s0 + (2 * NI + nb * HP + q) * BT + hoff) =
                    make_float4(hr[0], hr[1], hr[2], hr[3]);
                if (q < NI && it + 1 < Tt)
                    *(float4*)(s0 + (nb * NI + q) * BT + hoff) =
                        make_float4(xn0, xn1, xn2, xn3);
            }
        } else {
            if (act && it >= 1) {
                ull aif[4], ago[4];
                #pragma unroll
                for (int j = 0; j < 4; ++j) { aif[j] = bif; ago[j] = bgo; }
                // h0(it-1) in s0 h0 buf p (same rows A reads)
                acc40(s0 + (2 * NI + p * HP) * BT + hoff, WB + 4 * q, aif, ago);
                // h1(it-2) in s1 buf p
                acc40(s1 + p * HP * BT + hoff, WB + HP * (4 * HP) + 4 * q, aif, ago);
                float hr[4];
                #pragma unroll
                for (int j = 0; j < 4; ++j) {
                    float gi, gf, gg, go;
                    unpk2(aif[j], gi, gf); unpk2(ago[j], gg, go);
                    float i = sigm(gi), f = sigm(gf), g = tanh_(gg), o = sigm(go);
                    cst[j] = f * cst[j] + i * g;
                    hr[j] = o * tanh_(cst[j]);
                }
                *(float4*)(s1 + (nb * HP + q) * BT + hoff) =
                    make_float4(hr[0], hr[1], hr[2], hr[3]);
            }
        }

        __syncthreads();   // single per-block barrier
    }

    // ---- final projection from h1(Tt-1) in buf (Tt+1)&1 ----
    if (grp == 0 && act && q < Cc) {
        const int bufL = (Tt + 1) & 1;
        const float* hl = s1 + bufL * HP * BT + hoff;
        float a0 = bc[q], a1 = a0, a2 = a0, a3 = a0;
        #pragma unroll
        for (int k = 0; k < H; ++k) {
            float w = Wc[q * H + k];
            float4 hv = *(const float4*)(hl + k * BT);
            a0 += w * hv.x; a1 += w * hv.y; a2 += w * hv.z; a3 += w * hv.w;
        }
        out[(size_t)(bb0 + 0) * Cc + q] = a0;
        out[(size_t)(bb0 + 1) * Cc + q] = a1;
        out[(size_t)(bb0 + 2) * Cc + q] = a2;
        out[(size_t)(bb0 + 3) * Cc + q] = a3;
    }
}

extern "C" void kernel_launch(void* const* d_in, const int* in_sizes, int n_in,
                              void* d_out, int out_size) {
    const float* x    = (const float*)d_in[0];
    const float* Wih0 = (const float*)d_in[1];
    const float* Whh0 = (const float*)d_in[2];
    const float* b0   = (const float*)d_in[3];
    const float* Wih1 = (const float*)d_in[4];
    const float* Whh1 = (const float*)d_in[5];
    const float* b1   = (const float*)d_in[6];
    const float* Wc   = (const float*)d_in[7];
    const float* bc   = (const float*)d_in[8];

    const int smem_bytes = SMEM_FLOATS * (int)sizeof(float);
    cudaFuncSetAttribute(lstm_kernel, cudaFuncAttributeMaxDynamicSharedMemorySize, smem_bytes);
    lstm_kernel<<<Bsz / BT, NTHR, smem_bytes>>>(
        x, Wih0, Whh0, b0, Wih1, Whh1, b1, Wc, bc, (float*)d_out);
}